// round 13
// baseline (speedup 1.0000x reference)
#include <cuda_runtime.h>
#include <cuda_fp16.h>
#include <cstdint>

// ==========================================================================
// LSTM (relu candidate/output) + linear head via mma.sync m16n8k16 fp16
// B=65536, T=12, F=1, H=128.
// R13: R12 + REAL half-step phase stagger for group 1 (~2600 cyc via
//      clock64 spin, once). Groups share no barriers, so the anti-phase
//      offset persists -> the two pipelines' LDSM bursts interleave and
//      fill each other's epilogue lulls. Everything else identical to R12.
// ==========================================================================

#define TT       12
#define HH       128
#define GG       512
#define GTILE    32                      // rows per group tile
#define NTHREADS 512
#define NGT      2048                    // 65536 / 32
#define GRID     148
#define NGROUPS  (GRID * 2)              // 296
#define PADK     136                     // halfs per row (128 data + 8 pad)
#define ROWB     (PADK * 2)              // 272 bytes
#define REDP     36                      // red row pitch (floats), bank-spread

// ---- shared memory layout (bytes) ----
#define BT_OFF    0
#define BT_BYTES  (GG * ROWB)            // 139264 : R^T fp16, i/f/o rows x0.5
#define A_BASE    (BT_OFF + BT_BYTES)    // 4 h buffers: [g][buf] 32x272
#define AG_BYTES  (GTILE * ROWB)         // 8704
#define KP_OFF    (A_BASE + 4 * AG_BYTES)        // float4[128] kernel (i/f/o x0.5)
#define BP_OFF    (KP_OFF + 2048)                // float4[128] bias (i/f/o x0.5)
#define RED_BASE  (BP_OFF + 2048)                // float[2][32*REDP]
#define SMEM_TOTAL (RED_BASE + 2 * GTILE * REDP * 4)

__device__ __forceinline__ uint32_t s2u(const void* p) {
    uint32_t a;
    asm("{ .reg .u64 t; cvta.to.shared.u64 t, %1; cvt.u32.u64 %0, t; }" : "=r"(a) : "l"(p));
    return a;
}

#define LDSM4(r0, r1, r2, r3, addr) \
    asm volatile("ldmatrix.sync.aligned.m8n8.x4.shared.b16 {%0,%1,%2,%3}, [%4];" \
                 : "=r"(r0), "=r"(r1), "=r"(r2), "=r"(r3) : "r"(addr))

#define MMA16816(d0, d1, d2, d3, a0, a1, a2, a3, b0, b1) \
    asm volatile("mma.sync.aligned.m16n8k16.row.col.f32.f16.f16.f32 " \
                 "{%0,%1,%2,%3}, {%4,%5,%6,%7}, {%8,%9}, {%0,%1,%2,%3};" \
                 : "+f"(d0), "+f"(d1), "+f"(d2), "+f"(d3) \
                 : "r"(a0), "r"(a1), "r"(a2), "r"(a3), "r"(b0), "r"(b1))

// Input v is PRE-HALVED (i/f/o weights scaled 0.5): sigmoid = 0.5*tanh(v)+0.5
__device__ __forceinline__ float sigmoid_pre(float v) {
    float t;
    asm("tanh.approx.f32 %0, %1;" : "=f"(t) : "f"(v));
    return fmaf(0.5f, t, 0.5f);
}

__global__ __launch_bounds__(NTHREADS, 1)
void lstm_kernel(const float* __restrict__ x, const float* __restrict__ kern,
                 const float* __restrict__ rk, const float* __restrict__ bias,
                 const float* __restrict__ Wd, const float* __restrict__ bd,
                 float* __restrict__ out) {
    extern __shared__ char smem[];
    const uint32_t base = s2u(smem);
    const int tid  = threadIdx.x;
    const int lane = tid & 31;
    const int wid  = tid >> 5;
    const int g    = wid >> 3;       // pipeline group 0/1 (8 warps each)
    const int Q    = wid & 7;        // N-eighth: 64 perm cols = 16 units
    const int wtid = tid & 255;      // thread id within group
    const int t4   = lane >> 2;
    const int j    = lane & 3;

    __half* bt  = (__half*)(smem + BT_OFF);
    float*  kp  = (float*)(smem + KP_OFF);
    float*  bp  = (float*)(smem + BP_OFF);
    float*  redg = (float*)(smem + RED_BASE + g * (GTILE * REDP * 4));

    // ---- one-time init (verified permutations + exact 0.5 prescale) ----
    for (int i = tid; i < HH * GG; i += NTHREADS) {
        int ks = i >> 9, col = i & 511;
        int u = col & 127, gt = col >> 7;
        int n = 16 * (u >> 2) + 8 * (gt >> 1) + 2 * (u & 3) + (gt & 1);
        int kk = (ks & 3) * 32 + (ks >> 2);
        float sc = (gt == 2) ? 1.0f : 0.5f;
        bt[n * PADK + kk] = __float2half(rk[i] * sc);
    }
    for (int col = tid; col < GG; col += NTHREADS) {
        int u = col & 127, gt = col >> 7;
        float sc = (gt == 2) ? 1.0f : 0.5f;
        kp[u * 4 + gt] = kern[col] * sc;
        bp[u * 4 + gt] = bias[col] * sc;
    }
    // head weights for this thread's 4 units + bias (register-resident)
    float wdv[4];
#pragma unroll
    for (int pp = 0; pp < 4; pp++) wdv[pp] = Wd[16 * Q + 4 * pp + j];
    const float bd0 = bd[0];

    __syncthreads();   // ONLY CTA-wide sync; groups free-run afterwards

    // one-time HALF-STEP stagger for group 1 (~2600 cyc). Groups share no
    // barriers afterwards, so this anti-phase offset persists for the whole
    // kernel: group 1's LDSM bursts land in group 0's epilogue lulls.
    if (g == 1) {
        unsigned long long t0 = clock64();
        while (clock64() - t0 < 2600ULL) {}
    }

    const uint32_t ag0 = base + A_BASE + (uint32_t)g * 2u * AG_BYTES;
    const uint32_t ag1 = ag0 + AG_BYTES;

    const uint32_t lrow = (uint32_t)((lane & 7) + (lane & 8));
    const uint32_t lcol = (uint32_t)((lane >> 4) << 4);
    const uint32_t a_rel   = lrow * ROWB + lcol;
    const uint32_t bt_base = base + BT_OFF + ((uint32_t)Q * 64u + lrow) * ROWB + lcol;

    const int r0 = t4;
    uint32_t st_rel[4];
#pragma unroll
    for (int rr = 0; rr < 4; rr++)
        st_rel[rr] = (uint32_t)((r0 + 8 * rr) * ROWB + 64 * j + 8 * Q);

    const float4* kp4 = (const float4*)kp;
    const float4* bp4 = (const float4*)bp;
    const int bid = g + 1;

    // ---- persistent per-group tile loop ----
    for (int tile = blockIdx.x * 2 + g; tile < NGT; tile += NGROUPS) {
        const int b0 = tile * GTILE;
        const float* xg0 = x + (size_t)(b0 + r0) * TT;

        float c[16];
        float xr[4];
#pragma unroll
        for (int rr = 0; rr < 4; rr++) xr[rr] = __ldg(xg0 + rr * (8 * TT));

        // ---- t = 0 peeled (h0=0): z = x*k + b ; writes buf1 ----
        {
            uint32_t hw[4][2];
            float hprev[4];
#pragma unroll
            for (int pp = 0; pp < 4; pp++) {
                const int u = 16 * Q + 4 * pp + j;
                const float4 kv = kp4[u];
                const float4 bv = bp4[u];
#pragma unroll
                for (int rr = 0; rr < 4; rr++) {
                    float zi = fmaf(xr[rr], kv.x, bv.x);
                    float zg = fmaf(xr[rr], kv.z, bv.z);
                    float zo = fmaf(xr[rr], kv.w, bv.w);
                    float ig = sigmoid_pre(zi), og = sigmoid_pre(zo);
                    float cn = ig * fmaxf(zg, 0.0f);
                    c[4 * pp + rr] = cn;
                    float hv = og * fmaxf(cn, 0.0f);
                    if ((pp & 1) == 0) hprev[rr] = hv;
                    else {
                        __half2 h2 = __floats2half2_rn(hprev[rr], hv);
                        hw[rr][pp >> 1] = *(uint32_t*)&h2;
                    }
                }
            }
#pragma unroll
            for (int rr = 0; rr < 4; rr++)
                *(uint2*)(smem + (ag1 - base) + st_rel[rr]) = make_uint2(hw[rr][0], hw[rr][1]);
        }

        // ---- t = 1..10 ----
#pragma unroll 1
        for (int t = 1; t < TT - 1; t++) {
            asm volatile("bar.sync %0, %1;" :: "r"(bid), "n"(256) : "memory");

            const uint32_t rbase = (t & 1) ? ag1 : ag0;
            char* wbase = smem + (((t & 1) ? ag0 : ag1) - base);

            // x LDGs issued first: latency hidden behind LDSM/MMA
#pragma unroll
            for (int rr = 0; rr < 4; rr++) xr[rr] = __ldg(xg0 + rr * (8 * TT) + t);

            uint32_t a[2][8][4];
#pragma unroll
            for (int mt = 0; mt < 2; mt++)
#pragma unroll
                for (int kb = 0; kb < 8; kb++)
                    LDSM4(a[mt][kb][0], a[mt][kb][1], a[mt][kb][2], a[mt][kb][3],
                          rbase + a_rel + (uint32_t)mt * 16u * ROWB + (uint32_t)kb * 32u);

            uint32_t hw[4][2];
            float hprev[4];

#pragma unroll 2
            for (int pp = 0; pp < 4; pp++) {
                const int u = 16 * Q + 4 * pp + j;
                const float4 kv = kp4[u];
                const float4 bv = bp4[u];

                float d[16];
#pragma unroll
                for (int rr = 0; rr < 4; rr++) {
                    const int o = (rr >> 1) * 8 + (rr & 1) * 2;
                    d[o]     = fmaf(xr[rr], kv.x, bv.x);
                    d[o + 1] = fmaf(xr[rr], kv.y, bv.y);
                    d[o + 4] = fmaf(xr[rr], kv.z, bv.z);
                    d[o + 5] = fmaf(xr[rr], kv.w, bv.w);
                }

                const uint32_t bta = bt_base + (uint32_t)pp * (16u * ROWB);
#pragma unroll
                for (int kb = 0; kb < 8; kb++) {
                    uint32_t bq0, bq1, bq2, bq3;
                    LDSM4(bq0, bq1, bq2, bq3, bta + (uint32_t)kb * 32u);
                    MMA16816(d[0],  d[1],  d[2],  d[3],
                             a[0][kb][0], a[0][kb][1], a[0][kb][2], a[0][kb][3], bq0, bq2);
                    MMA16816(d[4],  d[5],  d[6],  d[7],
                             a[0][kb][0], a[0][kb][1], a[0][kb][2], a[0][kb][3], bq1, bq3);
                    MMA16816(d[8],  d[9],  d[10], d[11],
                             a[1][kb][0], a[1][kb][1], a[1][kb][2], a[1][kb][3], bq0, bq2);
                    MMA16816(d[12], d[13], d[14], d[15],
                             a[1][kb][0], a[1][kb][1], a[1][kb][2], a[1][kb][3], bq1, bq3);
                }

#pragma unroll
                for (int rr = 0; rr < 4; rr++) {
                    const int o = (rr >> 1) * 8 + (rr & 1) * 2;
                    float ig = sigmoid_pre(d[o]);
                    float fg = sigmoid_pre(d[o + 1]);
                    float og = sigmoid_pre(d[o + 5]);
                    float cn = fmaf(fg, c[4 * pp + rr], ig * fmaxf(d[o + 4], 0.0f));
                    c[4 * pp + rr] = cn;
                    float hv = og * fmaxf(cn, 0.0f);
                    if ((pp & 1) == 0) hprev[rr] = hv;
                    else {
                        __half2 h2 = __floats2half2_rn(hprev[rr], hv);
                        hw[rr][pp >> 1] = *(uint32_t*)&h2;
                    }
                }
            }

#pragma unroll
            for (int rr = 0; rr < 4; rr++)
                *(uint2*)(wbase + st_rel[rr]) = make_uint2(hw[rr][0], hw[rr][1]);
        }

        // ---- t = 11 peeled: no h writeback; ps = sum h*Wd in regs ----
        {
            asm volatile("bar.sync %0, %1;" :: "r"(bid), "n"(256) : "memory");
            const uint32_t rbase = ag1;   // t=11 odd -> reads buf1

#pragma unroll
            for (int rr = 0; rr < 4; rr++) xr[rr] = __ldg(xg0 + rr * (8 * TT) + 11);

            uint32_t a[2][8][4];
#pragma unroll
            for (int mt = 0; mt < 2; mt++)
#pragma unroll
                for (int kb = 0; kb < 8; kb++)
                    LDSM4(a[mt][kb][0], a[mt][kb][1], a[mt][kb][2], a[mt][kb][3],
                          rbase + a_rel + (uint32_t)mt * 16u * ROWB + (uint32_t)kb * 32u);

            float ps[4] = {0.f, 0.f, 0.f, 0.f};

#pragma unroll 2
            for (int pp = 0; pp < 4; pp++) {
                const int u = 16 * Q + 4 * pp + j;
                const float4 kv = kp4[u];
                const float4 bv = bp4[u];

                float d[16];
#pragma unroll
                for (int rr = 0; rr < 4; rr++) {
                    const int o = (rr >> 1) * 8 + (rr & 1) * 2;
                    d[o]     = fmaf(xr[rr], kv.x, bv.x);
                    d[o + 1] = fmaf(xr[rr], kv.y, bv.y);
                    d[o + 4] = fmaf(xr[rr], kv.z, bv.z);
                    d[o + 5] = fmaf(xr[rr], kv.w, bv.w);
                }

                const uint32_t bta = bt_base + (uint32_t)pp * (16u * ROWB);
#pragma unroll
                for (int kb = 0; kb < 8; kb++) {
                    uint32_t bq0, bq1, bq2, bq3;
                    LDSM4(bq0, bq1, bq2, bq3, bta + (uint32_t)kb * 32u);
                    MMA16816(d[0],  d[1],  d[2],  d[3],
                             a[0][kb][0], a[0][kb][1], a[0][kb][2], a[0][kb][3], bq0, bq2);
                    MMA16816(d[4],  d[5],  d[6],  d[7],
                             a[0][kb][0], a[0][kb][1], a[0][kb][2], a[0][kb][3], bq1, bq3);
                    MMA16816(d[8],  d[9],  d[10], d[11],
                             a[1][kb][0], a[1][kb][1], a[1][kb][2], a[1][kb][3], bq0, bq2);
                    MMA16816(d[12], d[13], d[14], d[15],
                             a[1][kb][0], a[1][kb][1], a[1][kb][2], a[1][kb][3], bq1, bq3);
                }

#pragma unroll
                for (int rr = 0; rr < 4; rr++) {
                    const int o = (rr >> 1) * 8 + (rr & 1) * 2;
                    float ig = sigmoid_pre(d[o]);
                    float fg = sigmoid_pre(d[o + 1]);
                    float og = sigmoid_pre(d[o + 5]);
                    float cn = fmaf(fg, c[4 * pp + rr], ig * fmaxf(d[o + 4], 0.0f));
                    float hv = og * fmaxf(cn, 0.0f);
                    ps[rr] = fmaf(hv, wdv[pp], ps[rr]);
                }
            }

#pragma unroll
            for (int rr = 0; rr < 4; rr++)
                redg[(r0 + 8 * rr) * REDP + Q * 4 + j] = ps[rr];
        }

        asm volatile("bar.sync %0, %1;" :: "r"(bid), "n"(256) : "memory");
        if (wtid < GTILE) {
            const float4* p = (const float4*)(redg + wtid * REDP);
            float4 s0 = p[0], s1 = p[1], s2 = p[2], s3 = p[3];
            float4 s4 = p[4], s5 = p[5], s6 = p[6], s7 = p[7];
            float s = (((s0.x + s0.y) + (s0.z + s0.w)) + ((s1.x + s1.y) + (s1.z + s1.w)))
                    + (((s2.x + s2.y) + (s2.z + s2.w)) + ((s3.x + s3.y) + (s3.z + s3.w)))
                    + (((s4.x + s4.y) + (s4.z + s4.w)) + ((s5.x + s5.y) + (s5.z + s5.w)))
                    + (((s6.x + s6.y) + (s6.z + s6.w)) + ((s7.x + s7.y) + (s7.z + s7.w)));
            out[b0 + wtid] = s + bd0;
        }
    }
}

extern "C" void kernel_launch(void* const* d_in, const int* in_sizes, int n_in,
                              void* d_out, int out_size) {
    const float* x    = (const float*)d_in[0];
    const float* kern = (const float*)d_in[1];
    const float* rk   = (const float*)d_in[2];
    const float* bias = (const float*)d_in[3];
    const float* Wd   = (const float*)d_in[4];
    const float* bd   = (const float*)d_in[5];
    float* out = (float*)d_out;

    cudaFuncSetAttribute(lstm_kernel, cudaFuncAttributeMaxDynamicSharedMemorySize, SMEM_TOTAL);
    lstm_kernel<<<GRID, NTHREADS, SMEM_TOTAL>>>(x, kern, rk, bias, Wd, bd, out);
}

// round 14
// speedup vs baseline: 1.0915x; 1.0915x over previous
#include <cuda_runtime.h>
#include <cuda_fp16.h>
#include <cstdint>

// ==========================================================================
// LSTM (relu candidate/output) + linear head via mma.sync m16n8k16 fp16
// B=65536, T=12, F=1, H=128.
// R14: R12 core (319.5us, rel_err 2.9e-5) with register-pressure relief so
//      ptxas can hoist next-pp B-LDSMs into the epilogue shadow:
//      - hw[] pack array removed (immediate STS.32 h stores)
//      - st_rel[] removed (addresses recomputed per store)
//      - pp loop fully unrolled
//      - neutral clock64 stagger removed
// ==========================================================================

#define TT       12
#define HH       128
#define GG       512
#define GTILE    32                      // rows per group tile
#define NTHREADS 512
#define NGT      2048                    // 65536 / 32
#define GRID     148
#define NGROUPS  (GRID * 2)              // 296
#define PADK     136                     // halfs per row (128 data + 8 pad)
#define ROWB     (PADK * 2)              // 272 bytes
#define REDP     36                      // red row pitch (floats), bank-spread

// ---- shared memory layout (bytes) ----
#define BT_OFF    0
#define BT_BYTES  (GG * ROWB)            // 139264 : R^T fp16, i/f/o rows x0.5
#define A_BASE    (BT_OFF + BT_BYTES)    // 4 h buffers: [g][buf] 32x272
#define AG_BYTES  (GTILE * ROWB)         // 8704
#define KP_OFF    (A_BASE + 4 * AG_BYTES)        // float4[128] kernel (i/f/o x0.5)
#define BP_OFF    (KP_OFF + 2048)                // float4[128] bias (i/f/o x0.5)
#define RED_BASE  (BP_OFF + 2048)                // float[2][32*REDP]
#define SMEM_TOTAL (RED_BASE + 2 * GTILE * REDP * 4)

__device__ __forceinline__ uint32_t s2u(const void* p) {
    uint32_t a;
    asm("{ .reg .u64 t; cvta.to.shared.u64 t, %1; cvt.u32.u64 %0, t; }" : "=r"(a) : "l"(p));
    return a;
}

#define LDSM4(r0, r1, r2, r3, addr) \
    asm volatile("ldmatrix.sync.aligned.m8n8.x4.shared.b16 {%0,%1,%2,%3}, [%4];" \
                 : "=r"(r0), "=r"(r1), "=r"(r2), "=r"(r3) : "r"(addr))

#define MMA16816(d0, d1, d2, d3, a0, a1, a2, a3, b0, b1) \
    asm volatile("mma.sync.aligned.m16n8k16.row.col.f32.f16.f16.f32 " \
                 "{%0,%1,%2,%3}, {%4,%5,%6,%7}, {%8,%9}, {%0,%1,%2,%3};" \
                 : "+f"(d0), "+f"(d1), "+f"(d2), "+f"(d3) \
                 : "r"(a0), "r"(a1), "r"(a2), "r"(a3), "r"(b0), "r"(b1))

#define STS32(addr, v) \
    asm volatile("st.shared.b32 [%0], %1;" :: "r"(addr), "r"(v) : "memory")

// Input v is PRE-HALVED (i/f/o weights scaled 0.5): sigmoid = 0.5*tanh(v)+0.5
__device__ __forceinline__ float sigmoid_pre(float v) {
    float t;
    asm("tanh.approx.f32 %0, %1;" : "=f"(t) : "f"(v));
    return fmaf(0.5f, t, 0.5f);
}

__global__ __launch_bounds__(NTHREADS, 1)
void lstm_kernel(const float* __restrict__ x, const float* __restrict__ kern,
                 const float* __restrict__ rk, const float* __restrict__ bias,
                 const float* __restrict__ Wd, const float* __restrict__ bd,
                 float* __restrict__ out) {
    extern __shared__ char smem[];
    const uint32_t base = s2u(smem);
    const int tid  = threadIdx.x;
    const int lane = tid & 31;
    const int wid  = tid >> 5;
    const int g    = wid >> 3;       // pipeline group 0/1 (8 warps each)
    const int Q    = wid & 7;        // N-eighth: 64 perm cols = 16 units
    const int wtid = tid & 255;      // thread id within group
    const int t4   = lane >> 2;
    const int j    = lane & 3;

    __half* bt  = (__half*)(smem + BT_OFF);
    float*  kp  = (float*)(smem + KP_OFF);
    float*  bp  = (float*)(smem + BP_OFF);
    float*  redg = (float*)(smem + RED_BASE + g * (GTILE * REDP * 4));

    // ---- one-time init (verified permutations + exact 0.5 prescale) ----
    for (int i = tid; i < HH * GG; i += NTHREADS) {
        int ks = i >> 9, col = i & 511;
        int u = col & 127, gt = col >> 7;
        int n = 16 * (u >> 2) + 8 * (gt >> 1) + 2 * (u & 3) + (gt & 1);
        int kk = (ks & 3) * 32 + (ks >> 2);
        float sc = (gt == 2) ? 1.0f : 0.5f;
        bt[n * PADK + kk] = __float2half(rk[i] * sc);
    }
    for (int col = tid; col < GG; col += NTHREADS) {
        int u = col & 127, gt = col >> 7;
        float sc = (gt == 2) ? 1.0f : 0.5f;
        kp[u * 4 + gt] = kern[col] * sc;
        bp[u * 4 + gt] = bias[col] * sc;
    }
    // head weights for this thread's 4 units + bias (register-resident)
    float wdv[4];
#pragma unroll
    for (int pp = 0; pp < 4; pp++) wdv[pp] = Wd[16 * Q + 4 * pp + j];
    const float bd0 = bd[0];

    __syncthreads();   // ONLY CTA-wide sync; groups free-run afterwards

    const uint32_t ag0 = base + A_BASE + (uint32_t)g * 2u * AG_BYTES;
    const uint32_t ag1 = ag0 + AG_BYTES;

    const uint32_t lrow = (uint32_t)((lane & 7) + (lane & 8));
    const uint32_t lcol = (uint32_t)((lane >> 4) << 4);
    const uint32_t a_rel   = lrow * ROWB + lcol;
    const uint32_t bt_base = base + BT_OFF + ((uint32_t)Q * 64u + lrow) * ROWB + lcol;

    const int r0 = t4;
    // h-store base for rr=0 (row r0), this thread's column window start:
    // unit u=16Q+4pp+j -> byte 64j + 8Q + 2pp within row
    const uint32_t hst0 = (uint32_t)(r0 * ROWB + 64 * j + 8 * Q);

    const float4* kp4 = (const float4*)kp;
    const float4* bp4 = (const float4*)bp;
    const int bid = g + 1;

    // ---- persistent per-group tile loop ----
    for (int tile = blockIdx.x * 2 + g; tile < NGT; tile += NGROUPS) {
        const int b0 = tile * GTILE;
        const float* xg0 = x + (size_t)(b0 + r0) * TT;

        float c[16];
        float xr[4];
#pragma unroll
        for (int rr = 0; rr < 4; rr++) xr[rr] = __ldg(xg0 + rr * (8 * TT));

        // ---- t = 0 peeled (h0=0): z = x*k + b ; writes buf1 ----
        {
            const uint32_t wb = ag1 + hst0;
            float hprev[4];
#pragma unroll
            for (int pp = 0; pp < 4; pp++) {
                const int u = 16 * Q + 4 * pp + j;
                const float4 kv = kp4[u];
                const float4 bv = bp4[u];
#pragma unroll
                for (int rr = 0; rr < 4; rr++) {
                    float zi = fmaf(xr[rr], kv.x, bv.x);
                    float zg = fmaf(xr[rr], kv.z, bv.z);
                    float zo = fmaf(xr[rr], kv.w, bv.w);
                    float ig = sigmoid_pre(zi), og = sigmoid_pre(zo);
                    float cn = ig * fmaxf(zg, 0.0f);
                    c[4 * pp + rr] = cn;
                    float hv = og * fmaxf(cn, 0.0f);
                    if ((pp & 1) == 0) hprev[rr] = hv;
                    else {
                        __half2 h2 = __floats2half2_rn(hprev[rr], hv);
                        STS32(wb + (uint32_t)(rr * 8 * ROWB + 2 * (pp - 1)),
                              *(uint32_t*)&h2);
                    }
                }
            }
        }

        // ---- t = 1..10 ----
#pragma unroll 1
        for (int t = 1; t < TT - 1; t++) {
            asm volatile("bar.sync %0, %1;" :: "r"(bid), "n"(256) : "memory");

            const uint32_t rbase = (t & 1) ? ag1 : ag0;
            const uint32_t wb = ((t & 1) ? ag0 : ag1) + hst0;

            // x LDGs issued first: latency hidden behind LDSM/MMA
#pragma unroll
            for (int rr = 0; rr < 4; rr++) xr[rr] = __ldg(xg0 + rr * (8 * TT) + t);

            uint32_t a[2][8][4];
#pragma unroll
            for (int mt = 0; mt < 2; mt++)
#pragma unroll
                for (int kb = 0; kb < 8; kb++)
                    LDSM4(a[mt][kb][0], a[mt][kb][1], a[mt][kb][2], a[mt][kb][3],
                          rbase + a_rel + (uint32_t)mt * 16u * ROWB + (uint32_t)kb * 32u);

            float hprev[4];

#pragma unroll
            for (int pp = 0; pp < 4; pp++) {
                const int u = 16 * Q + 4 * pp + j;
                const float4 kv = kp4[u];
                const float4 bv = bp4[u];

                float d[16];
#pragma unroll
                for (int rr = 0; rr < 4; rr++) {
                    const int o = (rr >> 1) * 8 + (rr & 1) * 2;
                    d[o]     = fmaf(xr[rr], kv.x, bv.x);
                    d[o + 1] = fmaf(xr[rr], kv.y, bv.y);
                    d[o + 4] = fmaf(xr[rr], kv.z, bv.z);
                    d[o + 5] = fmaf(xr[rr], kv.w, bv.w);
                }

                const uint32_t bta = bt_base + (uint32_t)pp * (16u * ROWB);
#pragma unroll
                for (int kb = 0; kb < 8; kb++) {
                    uint32_t bq0, bq1, bq2, bq3;
                    LDSM4(bq0, bq1, bq2, bq3, bta + (uint32_t)kb * 32u);
                    MMA16816(d[0],  d[1],  d[2],  d[3],
                             a[0][kb][0], a[0][kb][1], a[0][kb][2], a[0][kb][3], bq0, bq2);
                    MMA16816(d[4],  d[5],  d[6],  d[7],
                             a[0][kb][0], a[0][kb][1], a[0][kb][2], a[0][kb][3], bq1, bq3);
                    MMA16816(d[8],  d[9],  d[10], d[11],
                             a[1][kb][0], a[1][kb][1], a[1][kb][2], a[1][kb][3], bq0, bq2);
                    MMA16816(d[12], d[13], d[14], d[15],
                             a[1][kb][0], a[1][kb][1], a[1][kb][2], a[1][kb][3], bq1, bq3);
                }

#pragma unroll
                for (int rr = 0; rr < 4; rr++) {
                    const int o = (rr >> 1) * 8 + (rr & 1) * 2;
                    float ig = sigmoid_pre(d[o]);
                    float fg = sigmoid_pre(d[o + 1]);
                    float og = sigmoid_pre(d[o + 5]);
                    float cn = fmaf(fg, c[4 * pp + rr], ig * fmaxf(d[o + 4], 0.0f));
                    c[4 * pp + rr] = cn;
                    float hv = og * fmaxf(cn, 0.0f);
                    if ((pp & 1) == 0) hprev[rr] = hv;
                    else {
                        __half2 h2 = __floats2half2_rn(hprev[rr], hv);
                        STS32(wb + (uint32_t)(rr * 8 * ROWB + 2 * (pp - 1)),
                              *(uint32_t*)&h2);
                    }
                }
            }
        }

        // ---- t = 11 peeled: no h writeback; ps = sum h*Wd in regs ----
        {
            asm volatile("bar.sync %0, %1;" :: "r"(bid), "n"(256) : "memory");
            const uint32_t rbase = ag1;   // t=11 odd -> reads buf1

#pragma unroll
            for (int rr = 0; rr < 4; rr++) xr[rr] = __ldg(xg0 + rr * (8 * TT) + 11);

            uint32_t a[2][8][4];
#pragma unroll
            for (int mt = 0; mt < 2; mt++)
#pragma unroll
                for (int kb = 0; kb < 8; kb++)
                    LDSM4(a[mt][kb][0], a[mt][kb][1], a[mt][kb][2], a[mt][kb][3],
                          rbase + a_rel + (uint32_t)mt * 16u * ROWB + (uint32_t)kb * 32u);

            float ps[4] = {0.f, 0.f, 0.f, 0.f};

#pragma unroll
            for (int pp = 0; pp < 4; pp++) {
                const int u = 16 * Q + 4 * pp + j;
                const float4 kv = kp4[u];
                const float4 bv = bp4[u];

                float d[16];
#pragma unroll
                for (int rr = 0; rr < 4; rr++) {
                    const int o = (rr >> 1) * 8 + (rr & 1) * 2;
                    d[o]     = fmaf(xr[rr], kv.x, bv.x);
                    d[o + 1] = fmaf(xr[rr], kv.y, bv.y);
                    d[o + 4] = fmaf(xr[rr], kv.z, bv.z);
                    d[o + 5] = fmaf(xr[rr], kv.w, bv.w);
                }

                const uint32_t bta = bt_base + (uint32_t)pp * (16u * ROWB);
#pragma unroll
                for (int kb = 0; kb < 8; kb++) {
                    uint32_t bq0, bq1, bq2, bq3;
                    LDSM4(bq0, bq1, bq2, bq3, bta + (uint32_t)kb * 32u);
                    MMA16816(d[0],  d[1],  d[2],  d[3],
                             a[0][kb][0], a[0][kb][1], a[0][kb][2], a[0][kb][3], bq0, bq2);
                    MMA16816(d[4],  d[5],  d[6],  d[7],
                             a[0][kb][0], a[0][kb][1], a[0][kb][2], a[0][kb][3], bq1, bq3);
                    MMA16816(d[8],  d[9],  d[10], d[11],
                             a[1][kb][0], a[1][kb][1], a[1][kb][2], a[1][kb][3], bq0, bq2);
                    MMA16816(d[12], d[13], d[14], d[15],
                             a[1][kb][0], a[1][kb][1], a[1][kb][2], a[1][kb][3], bq1, bq3);
                }

#pragma unroll
                for (int rr = 0; rr < 4; rr++) {
                    const int o = (rr >> 1) * 8 + (rr & 1) * 2;
                    float ig = sigmoid_pre(d[o]);
                    float fg = sigmoid_pre(d[o + 1]);
                    float og = sigmoid_pre(d[o + 5]);
                    float cn = fmaf(fg, c[4 * pp + rr], ig * fmaxf(d[o + 4], 0.0f));
                    float hv = og * fmaxf(cn, 0.0f);
                    ps[rr] = fmaf(hv, wdv[pp], ps[rr]);
                }
            }

#pragma unroll
            for (int rr = 0; rr < 4; rr++)
                redg[(r0 + 8 * rr) * REDP + Q * 4 + j] = ps[rr];
        }

        asm volatile("bar.sync %0, %1;" :: "r"(bid), "n"(256) : "memory");
        if (wtid < GTILE) {
            const float4* p = (const float4*)(redg + wtid * REDP);
            float4 s0 = p[0], s1 = p[1], s2 = p[2], s3 = p[3];
            float4 s4 = p[4], s5 = p[5], s6 = p[6], s7 = p[7];
            float s = (((s0.x + s0.y) + (s0.z + s0.w)) + ((s1.x + s1.y) + (s1.z + s1.w)))
                    + (((s2.x + s2.y) + (s2.z + s2.w)) + ((s3.x + s3.y) + (s3.z + s3.w)))
                    + (((s4.x + s4.y) + (s4.z + s4.w)) + ((s5.x + s5.y) + (s5.z + s5.w)))
                    + (((s6.x + s6.y) + (s6.z + s6.w)) + ((s7.x + s7.y) + (s7.z + s7.w)));
            out[b0 + wtid] = s + bd0;
        }
    }
}

extern "C" void kernel_launch(void* const* d_in, const int* in_sizes, int n_in,
                              void* d_out, int out_size) {
    const float* x    = (const float*)d_in[0];
    const float* kern = (const float*)d_in[1];
    const float* rk   = (const float*)d_in[2];
    const float* bias = (const float*)d_in[3];
    const float* Wd   = (const float*)d_in[4];
    const float* bd   = (const float*)d_in[5];
    float* out = (float*)d_out;

    cudaFuncSetAttribute(lstm_kernel, cudaFuncAttributeMaxDynamicSharedMemorySize, SMEM_TOTAL);
    lstm_kernel<<<GRID, NTHREADS, SMEM_TOTAL>>>(x, kern, rk, bias, Wd, bd, out);
}

// round 16
// speedup vs baseline: 1.0988x; 1.0067x over previous
#include <cuda_runtime.h>
#include <cuda_fp16.h>
#include <cstdint>

// ==========================================================================
// LSTM (relu candidate/output) + linear head via mma.sync m16n8k16 fp16
// B=65536, T=12, F=1, H=128.
// R16 = R15 resubmit (infra failure last round, no GPU signal).
// R15: R14 (295.5us, rel_err 2.9e-5) + h-independent work hoisted ABOVE the
//      per-step barrier: x LDGs and the pp0 accumulator seed (x*k+b) execute
//      during the barrier wait, so the first B-LDSM/MMA issues immediately
//      after barrier release. Numerically identical to R14.
// ==========================================================================

#define TT       12
#define HH       128
#define GG       512
#define GTILE    32                      // rows per group tile
#define NTHREADS 512
#define NGT      2048                    // 65536 / 32
#define GRID     148
#define NGROUPS  (GRID * 2)              // 296
#define PADK     136                     // halfs per row (128 data + 8 pad)
#define ROWB     (PADK * 2)              // 272 bytes
#define REDP     36                      // red row pitch (floats), bank-spread

// ---- shared memory layout (bytes) ----
#define BT_OFF    0
#define BT_BYTES  (GG * ROWB)            // 139264 : R^T fp16, i/f/o rows x0.5
#define A_BASE    (BT_OFF + BT_BYTES)    // 4 h buffers: [g][buf] 32x272
#define AG_BYTES  (GTILE * ROWB)         // 8704
#define KP_OFF    (A_BASE + 4 * AG_BYTES)        // float4[128] kernel (i/f/o x0.5)
#define BP_OFF    (KP_OFF + 2048)                // float4[128] bias (i/f/o x0.5)
#define RED_BASE  (BP_OFF + 2048)                // float[2][32*REDP]
#define SMEM_TOTAL (RED_BASE + 2 * GTILE * REDP * 4)

__device__ __forceinline__ uint32_t s2u(const void* p) {
    uint32_t a;
    asm("{ .reg .u64 t; cvta.to.shared.u64 t, %1; cvt.u32.u64 %0, t; }" : "=r"(a) : "l"(p));
    return a;
}

#define LDSM4(r0, r1, r2, r3, addr) \
    asm volatile("ldmatrix.sync.aligned.m8n8.x4.shared.b16 {%0,%1,%2,%3}, [%4];" \
                 : "=r"(r0), "=r"(r1), "=r"(r2), "=r"(r3) : "r"(addr))

#define MMA16816(d0, d1, d2, d3, a0, a1, a2, a3, b0, b1) \
    asm volatile("mma.sync.aligned.m16n8k16.row.col.f32.f16.f16.f32 " \
                 "{%0,%1,%2,%3}, {%4,%5,%6,%7}, {%8,%9}, {%0,%1,%2,%3};" \
                 : "+f"(d0), "+f"(d1), "+f"(d2), "+f"(d3) \
                 : "r"(a0), "r"(a1), "r"(a2), "r"(a3), "r"(b0), "r"(b1))

#define STS32(addr, v) \
    asm volatile("st.shared.b32 [%0], %1;" :: "r"(addr), "r"(v) : "memory")

// Input v is PRE-HALVED (i/f/o weights scaled 0.5): sigmoid = 0.5*tanh(v)+0.5
__device__ __forceinline__ float sigmoid_pre(float v) {
    float t;
    asm("tanh.approx.f32 %0, %1;" : "=f"(t) : "f"(v));
    return fmaf(0.5f, t, 0.5f);
}

__global__ __launch_bounds__(NTHREADS, 1)
void lstm_kernel(const float* __restrict__ x, const float* __restrict__ kern,
                 const float* __restrict__ rk, const float* __restrict__ bias,
                 const float* __restrict__ Wd, const float* __restrict__ bd,
                 float* __restrict__ out) {
    extern __shared__ char smem[];
    const uint32_t base = s2u(smem);
    const int tid  = threadIdx.x;
    const int lane = tid & 31;
    const int wid  = tid >> 5;
    const int g    = wid >> 3;       // pipeline group 0/1 (8 warps each)
    const int Q    = wid & 7;        // N-eighth: 64 perm cols = 16 units
    const int wtid = tid & 255;      // thread id within group
    const int t4   = lane >> 2;
    const int j    = lane & 3;

    __half* bt  = (__half*)(smem + BT_OFF);
    float*  kp  = (float*)(smem + KP_OFF);
    float*  bp  = (float*)(smem + BP_OFF);
    float*  redg = (float*)(smem + RED_BASE + g * (GTILE * REDP * 4));

    // ---- one-time init (verified permutations + exact 0.5 prescale) ----
    for (int i = tid; i < HH * GG; i += NTHREADS) {
        int ks = i >> 9, col = i & 511;
        int u = col & 127, gt = col >> 7;
        int n = 16 * (u >> 2) + 8 * (gt >> 1) + 2 * (u & 3) + (gt & 1);
        int kk = (ks & 3) * 32 + (ks >> 2);
        float sc = (gt == 2) ? 1.0f : 0.5f;
        bt[n * PADK + kk] = __float2half(rk[i] * sc);
    }
    for (int col = tid; col < GG; col += NTHREADS) {
        int u = col & 127, gt = col >> 7;
        float sc = (gt == 2) ? 1.0f : 0.5f;
        kp[u * 4 + gt] = kern[col] * sc;
        bp[u * 4 + gt] = bias[col] * sc;
    }
    // head weights for this thread's 4 units + bias (register-resident)
    float wdv[4];
#pragma unroll
    for (int pp = 0; pp < 4; pp++) wdv[pp] = Wd[16 * Q + 4 * pp + j];
    const float bd0 = bd[0];

    __syncthreads();   // ONLY CTA-wide sync; groups free-run afterwards

    const uint32_t ag0 = base + A_BASE + (uint32_t)g * 2u * AG_BYTES;
    const uint32_t ag1 = ag0 + AG_BYTES;

    const uint32_t lrow = (uint32_t)((lane & 7) + (lane & 8));
    const uint32_t lcol = (uint32_t)((lane >> 4) << 4);
    const uint32_t a_rel   = lrow * ROWB + lcol;
    const uint32_t bt_base = base + BT_OFF + ((uint32_t)Q * 64u + lrow) * ROWB + lcol;

    const int r0 = t4;
    // h-store base for rr=0 (row r0): unit u=16Q+4pp+j -> byte 64j+8Q+2pp
    const uint32_t hst0 = (uint32_t)(r0 * ROWB + 64 * j + 8 * Q);

    const float4* kp4 = (const float4*)kp;
    const float4* bp4 = (const float4*)bp;
    const int bid = g + 1;

    // ---- persistent per-group tile loop ----
    for (int tile = blockIdx.x * 2 + g; tile < NGT; tile += NGROUPS) {
        const int b0 = tile * GTILE;
        const float* xg0 = x + (size_t)(b0 + r0) * TT;

        float c[16];
        float xr[4];
#pragma unroll
        for (int rr = 0; rr < 4; rr++) xr[rr] = __ldg(xg0 + rr * (8 * TT));

        // ---- t = 0 peeled (h0=0): z = x*k + b ; writes buf1 ----
        {
            const uint32_t wb = ag1 + hst0;
            float hprev[4];
#pragma unroll
            for (int pp = 0; pp < 4; pp++) {
                const int u = 16 * Q + 4 * pp + j;
                const float4 kv = kp4[u];
                const float4 bv = bp4[u];
#pragma unroll
                for (int rr = 0; rr < 4; rr++) {
                    float zi = fmaf(xr[rr], kv.x, bv.x);
                    float zg = fmaf(xr[rr], kv.z, bv.z);
                    float zo = fmaf(xr[rr], kv.w, bv.w);
                    float ig = sigmoid_pre(zi), og = sigmoid_pre(zo);
                    float cn = ig * fmaxf(zg, 0.0f);
                    c[4 * pp + rr] = cn;
                    float hv = og * fmaxf(cn, 0.0f);
                    if ((pp & 1) == 0) hprev[rr] = hv;
                    else {
                        __half2 h2 = __floats2half2_rn(hprev[rr], hv);
                        STS32(wb + (uint32_t)(rr * 8 * ROWB + 2 * (pp - 1)),
                              *(uint32_t*)&h2);
                    }
                }
            }
        }

        // ---- t = 1..10 ----
#pragma unroll 1
        for (int t = 1; t < TT - 1; t++) {
            // === h-independent pre-barrier work: overlaps barrier wait ===
#pragma unroll
            for (int rr = 0; rr < 4; rr++) xr[rr] = __ldg(xg0 + rr * (8 * TT) + t);

            float d[16];
            {   // seed accumulators for pp = 0
                const int u0 = 16 * Q + j;
                const float4 kv = kp4[u0];
                const float4 bv = bp4[u0];
#pragma unroll
                for (int rr = 0; rr < 4; rr++) {
                    const int o = (rr >> 1) * 8 + (rr & 1) * 2;
                    d[o]     = fmaf(xr[rr], kv.x, bv.x);
                    d[o + 1] = fmaf(xr[rr], kv.y, bv.y);
                    d[o + 4] = fmaf(xr[rr], kv.z, bv.z);
                    d[o + 5] = fmaf(xr[rr], kv.w, bv.w);
                }
            }

            asm volatile("bar.sync %0, %1;" :: "r"(bid), "n"(256) : "memory");

            const uint32_t rbase = (t & 1) ? ag1 : ag0;
            const uint32_t wb = ((t & 1) ? ag0 : ag1) + hst0;

            uint32_t a[2][8][4];
#pragma unroll
            for (int mt = 0; mt < 2; mt++)
#pragma unroll
                for (int kb = 0; kb < 8; kb++)
                    LDSM4(a[mt][kb][0], a[mt][kb][1], a[mt][kb][2], a[mt][kb][3],
                          rbase + a_rel + (uint32_t)mt * 16u * ROWB + (uint32_t)kb * 32u);

            float hprev[4];

#pragma unroll
            for (int pp = 0; pp < 4; pp++) {
                const int u = 16 * Q + 4 * pp + j;
                const float4 kv = kp4[u];
                const float4 bv = bp4[u];

                if (pp > 0) {   // pp0 seeded before the barrier
#pragma unroll
                    for (int rr = 0; rr < 4; rr++) {
                        const int o = (rr >> 1) * 8 + (rr & 1) * 2;
                        d[o]     = fmaf(xr[rr], kv.x, bv.x);
                        d[o + 1] = fmaf(xr[rr], kv.y, bv.y);
                        d[o + 4] = fmaf(xr[rr], kv.z, bv.z);
                        d[o + 5] = fmaf(xr[rr], kv.w, bv.w);
                    }
                }

                const uint32_t bta = bt_base + (uint32_t)pp * (16u * ROWB);
#pragma unroll
                for (int kb = 0; kb < 8; kb++) {
                    uint32_t bq0, bq1, bq2, bq3;
                    LDSM4(bq0, bq1, bq2, bq3, bta + (uint32_t)kb * 32u);
                    MMA16816(d[0],  d[1],  d[2],  d[3],
                             a[0][kb][0], a[0][kb][1], a[0][kb][2], a[0][kb][3], bq0, bq2);
                    MMA16816(d[4],  d[5],  d[6],  d[7],
                             a[0][kb][0], a[0][kb][1], a[0][kb][2], a[0][kb][3], bq1, bq3);
                    MMA16816(d[8],  d[9],  d[10], d[11],
                             a[1][kb][0], a[1][kb][1], a[1][kb][2], a[1][kb][3], bq0, bq2);
                    MMA16816(d[12], d[13], d[14], d[15],
                             a[1][kb][0], a[1][kb][1], a[1][kb][2], a[1][kb][3], bq1, bq3);
                }

#pragma unroll
                for (int rr = 0; rr < 4; rr++) {
                    const int o = (rr >> 1) * 8 + (rr & 1) * 2;
                    float ig = sigmoid_pre(d[o]);
                    float fg = sigmoid_pre(d[o + 1]);
                    float og = sigmoid_pre(d[o + 5]);
                    float cn = fmaf(fg, c[4 * pp + rr], ig * fmaxf(d[o + 4], 0.0f));
                    c[4 * pp + rr] = cn;
                    float hv = og * fmaxf(cn, 0.0f);
                    if ((pp & 1) == 0) hprev[rr] = hv;
                    else {
                        __half2 h2 = __floats2half2_rn(hprev[rr], hv);
                        STS32(wb + (uint32_t)(rr * 8 * ROWB + 2 * (pp - 1)),
                              *(uint32_t*)&h2);
                    }
                }
            }
        }

        // ---- t = 11 peeled: no h writeback; ps = sum h*Wd in regs ----
        {
            // pre-barrier h-independent work
#pragma unroll
            for (int rr = 0; rr < 4; rr++) xr[rr] = __ldg(xg0 + rr * (8 * TT) + 11);

            float d[16];
            {
                const int u0 = 16 * Q + j;
                const float4 kv = kp4[u0];
                const float4 bv = bp4[u0];
#pragma unroll
                for (int rr = 0; rr < 4; rr++) {
                    const int o = (rr >> 1) * 8 + (rr & 1) * 2;
                    d[o]     = fmaf(xr[rr], kv.x, bv.x);
                    d[o + 1] = fmaf(xr[rr], kv.y, bv.y);
                    d[o + 4] = fmaf(xr[rr], kv.z, bv.z);
                    d[o + 5] = fmaf(xr[rr], kv.w, bv.w);
                }
            }

            asm volatile("bar.sync %0, %1;" :: "r"(bid), "n"(256) : "memory");
            const uint32_t rbase = ag1;   // t=11 odd -> reads buf1

            uint32_t a[2][8][4];
#pragma unroll
            for (int mt = 0; mt < 2; mt++)
#pragma unroll
                for (int kb = 0; kb < 8; kb++)
                    LDSM4(a[mt][kb][0], a[mt][kb][1], a[mt][kb][2], a[mt][kb][3],
                          rbase + a_rel + (uint32_t)mt * 16u * ROWB + (uint32_t)kb * 32u);

            float ps[4] = {0.f, 0.f, 0.f, 0.f};

#pragma unroll
            for (int pp = 0; pp < 4; pp++) {
                const int u = 16 * Q + 4 * pp + j;
                const float4 kv = kp4[u];
                const float4 bv = bp4[u];

                if (pp > 0) {
#pragma unroll
                    for (int rr = 0; rr < 4; rr++) {
                        const int o = (rr >> 1) * 8 + (rr & 1) * 2;
                        d[o]     = fmaf(xr[rr], kv.x, bv.x);
                        d[o + 1] = fmaf(xr[rr], kv.y, bv.y);
                        d[o + 4] = fmaf(xr[rr], kv.z, bv.z);
                        d[o + 5] = fmaf(xr[rr], kv.w, bv.w);
                    }
                }

                const uint32_t bta = bt_base + (uint32_t)pp * (16u * ROWB);
#pragma unroll
                for (int kb = 0; kb < 8; kb++) {
                    uint32_t bq0, bq1, bq2, bq3;
                    LDSM4(bq0, bq1, bq2, bq3, bta + (uint32_t)kb * 32u);
                    MMA16816(d[0],  d[1],  d[2],  d[3],
                             a[0][kb][0], a[0][kb][1], a[0][kb][2], a[0][kb][3], bq0, bq2);
                    MMA16816(d[4],  d[5],  d[6],  d[7],
                             a[0][kb][0], a[0][kb][1], a[0][kb][2], a[0][kb][3], bq1, bq3);
                    MMA16816(d[8],  d[9],  d[10], d[11],
                             a[1][kb][0], a[1][kb][1], a[1][kb][2], a[1][kb][3], bq0, bq2);
                    MMA16816(d[12], d[13], d[14], d[15],
                             a[1][kb][0], a[1][kb][1], a[1][kb][2], a[1][kb][3], bq1, bq3);
                }

#pragma unroll
                for (int rr = 0; rr < 4; rr++) {
                    const int o = (rr >> 1) * 8 + (rr & 1) * 2;
                    float ig = sigmoid_pre(d[o]);
                    float fg = sigmoid_pre(d[o + 1]);
                    float og = sigmoid_pre(d[o + 5]);
                    float cn = fmaf(fg, c[4 * pp + rr], ig * fmaxf(d[o + 4], 0.0f));
                    float hv = og * fmaxf(cn, 0.0f);
                    ps[rr] = fmaf(hv, wdv[pp], ps[rr]);
                }
            }

#pragma unroll
            for (int rr = 0; rr < 4; rr++)
                redg[(r0 + 8 * rr) * REDP + Q * 4 + j] = ps[rr];
        }

        asm volatile("bar.sync %0, %1;" :: "r"(bid), "n"(256) : "memory");
        if (wtid < GTILE) {
            const float4* p = (const float4*)(redg + wtid * REDP);
            float4 s0 = p[0], s1 = p[1], s2 = p[2], s3 = p[3];
            float4 s4 = p[4], s5 = p[5], s6 = p[6], s7 = p[7];
            float s = (((s0.x + s0.y) + (s0.z + s0.w)) + ((s1.x + s1.y) + (s1.z + s1.w)))
                    + (((s2.x + s2.y) + (s2.z + s2.w)) + ((s3.x + s3.y) + (s3.z + s3.w)))
                    + (((s4.x + s4.y) + (s4.z + s4.w)) + ((s5.x + s5.y) + (s5.z + s5.w)))
                    + (((s6.x + s6.y) + (s6.z + s6.w)) + ((s7.x + s7.y) + (s7.z + s7.w)));
            out[b0 + wtid] = s + bd0;
        }
    }
}

extern "C" void kernel_launch(void* const* d_in, const int* in_sizes, int n_in,
                              void* d_out, int out_size) {
    const float* x    = (const float*)d_in[0];
    const float* kern = (const float*)d_in[1];
    const float* rk   = (const float*)d_in[2];
    const float* bias = (const float*)d_in[3];
    const float* Wd   = (const float*)d_in[4];
    const float* bd   = (const float*)d_in[5];
    float* out = (float*)d_out;

    cudaFuncSetAttribute(lstm_kernel, cudaFuncAttributeMaxDynamicSharedMemorySize, SMEM_TOTAL);
    lstm_kernel<<<GRID, NTHREADS, SMEM_TOTAL>>>(x, kern, rk, bias, Wd, bd, out);
}